// round 1
// baseline (speedup 1.0000x reference)
#include <cuda_runtime.h>

#define B     16
#define CIN   512
#define COUT  512
#define WDIM  512
#define RES   64
#define KS    3
#define LRELU 0.2f
#define GAINV 1.4142135623730951f

// Scratch (device globals: no allocation allowed)
__device__ float g_styles[B * CIN];    // [b, cin]
__device__ float g_wsq[COUT * CIN];    // sum_k weight^2
__device__ float g_dcoef[B * COUT];    // demod coefficients

// ---------------------------------------------------------------------------
// Kernel 1: styles[b,c] = (sum_d w[b,d]*affine_w[c,d]) * (1/sqrt(WDIM)) + affine_b[c]
// one warp per (b,c)
// ---------------------------------------------------------------------------
__global__ void styles_kernel(const float* __restrict__ w,
                              const float* __restrict__ aw,
                              const float* __restrict__ ab) {
    int warp = (blockIdx.x * blockDim.x + threadIdx.x) >> 5;
    int lane = threadIdx.x & 31;
    if (warp >= B * CIN) return;
    int b = warp / CIN, c = warp % CIN;
    const float* wr = w + b * WDIM;
    const float* ar = aw + c * WDIM;
    float sum = 0.f;
    for (int d = lane; d < WDIM; d += 32) sum += wr[d] * ar[d];
    #pragma unroll
    for (int o = 16; o; o >>= 1) sum += __shfl_xor_sync(0xffffffffu, sum, o);
    if (lane == 0) g_styles[warp] = sum * rsqrtf((float)WDIM) + ab[c];
}

// ---------------------------------------------------------------------------
// Kernel 2: wsq[o,c] = sum over 9 taps of weight^2
// ---------------------------------------------------------------------------
__global__ void wsq_kernel(const float* __restrict__ weight) {
    int i = blockIdx.x * blockDim.x + threadIdx.x;
    if (i >= COUT * CIN) return;
    const float* p = weight + i * 9;
    float s = 0.f;
    #pragma unroll
    for (int k = 0; k < 9; k++) s += p[k] * p[k];
    g_wsq[i] = s;
}

// ---------------------------------------------------------------------------
// Kernel 3: dcoef[b,o] = rsqrt( sum_c styles[b,c]^2 * wsq[o,c] + 1e-8 )
// one warp per (b,o)
// ---------------------------------------------------------------------------
__global__ void dcoef_kernel() {
    int warp = (blockIdx.x * blockDim.x + threadIdx.x) >> 5;
    int lane = threadIdx.x & 31;
    if (warp >= B * COUT) return;
    int b = warp / COUT, o = warp % COUT;
    const float* sr = g_styles + b * CIN;
    const float* wr = g_wsq + o * CIN;
    float sum = 0.f;
    for (int c = lane; c < CIN; c += 32) {
        float s = sr[c];
        sum += s * s * wr[c];
    }
    #pragma unroll
    for (int k = 16; k; k >>= 1) sum += __shfl_xor_sync(0xffffffffu, sum, k);
    if (lane == 0) g_dcoef[warp] = rsqrtf(sum + 1e-8f);
}

// ---------------------------------------------------------------------------
// Kernel 4: direct conv with style folded into x-load, demod+noise+bias+lrelu
// fused epilogue.
// Block: 1 batch x 32 oc x (16x16 px). 256 threads:
//   ocg = tid/64 (4 groups of 8 oc), pxg = tid%64 -> (row, 4 consecutive cols)
// cin chunked by 8 through shared memory.
// ---------------------------------------------------------------------------
#define OC_TILE 32
#define PXT     16
#define CC      8
#define XW      18   // PXT + 2 halo

__global__ __launch_bounds__(256) void conv_kernel(
    const float* __restrict__ x, const float* __restrict__ weight,
    const float* __restrict__ bias, const float* __restrict__ noise,
    const float* __restrict__ nstrength, float* __restrict__ out)
{
    __shared__ float sx[CC][XW * XW];       // 8 * 324 * 4B = 10.4 KB
    __shared__ float sw[CC][9][OC_TILE];    // 9.2 KB

    const int b    = blockIdx.z;
    const int oc0  = blockIdx.y * OC_TILE;
    const int tile = blockIdx.x;
    const int h0   = (tile >> 2) * PXT;
    const int w0   = (tile & 3) * PXT;

    const int tid  = threadIdx.x;
    const int ocg  = tid >> 6;        // 0..3
    const int pxg  = tid & 63;        // 0..63
    const int prow = pxg >> 2;        // 0..15
    const int pcol = (pxg & 3) * 4;   // 0,4,8,12

    float acc[8][4];
    #pragma unroll
    for (int i = 0; i < 8; i++)
        #pragma unroll
        for (int j = 0; j < 4; j++) acc[i][j] = 0.f;

    const float* styles_b = g_styles + b * CIN;

    for (int c0 = 0; c0 < CIN; c0 += CC) {
        // --- load x tile (with halo, zero pad) modulated by style ---
        #pragma unroll
        for (int idx = tid; idx < CC * XW * XW; idx += 256) {
            int cc  = idx / (XW * XW);
            int rem = idx - cc * (XW * XW);
            int r   = rem / XW;
            int col = rem - r * XW;
            int gh  = h0 - 1 + r;
            int gw  = w0 - 1 + col;
            float v = 0.f;
            if ((unsigned)gh < RES && (unsigned)gw < RES)
                v = x[(((size_t)b * CIN + c0 + cc) * RES + gh) * RES + gw]
                    * styles_b[c0 + cc];
            sx[cc][rem] = v;
        }
        // --- load weight chunk: sw[cc][tap][oc] ---
        #pragma unroll
        for (int idx = tid; idx < CC * 9 * OC_TILE; idx += 256) {
            int cc  = idx / (9 * OC_TILE);
            int rem = idx - cc * (9 * OC_TILE);
            int tap = rem / OC_TILE;
            int oc  = rem - tap * OC_TILE;
            sw[cc][tap][oc] = weight[(((size_t)(oc0 + oc)) * CIN + c0 + cc) * 9 + tap];
        }
        __syncthreads();

        // --- compute ---
        #pragma unroll
        for (int cc = 0; cc < CC; cc++) {
            #pragma unroll
            for (int tap = 0; tap < 9; tap++) {
                const int dy = tap / 3, dx = tap % 3;
                float wv[8];
                #pragma unroll
                for (int i = 0; i < 8; i++) wv[i] = sw[cc][tap][ocg * 8 + i];
                float xv[4];
                #pragma unroll
                for (int j = 0; j < 4; j++)
                    xv[j] = sx[cc][(prow + dy) * XW + pcol + j + dx];
                #pragma unroll
                for (int i = 0; i < 8; i++)
                    #pragma unroll
                    for (int j = 0; j < 4; j++)
                        acc[i][j] += wv[i] * xv[j];
            }
        }
        __syncthreads();
    }

    // --- epilogue: demod, noise, bias, lrelu, gain ---
    const float ns = nstrength[0];
    const int h = h0 + prow;
    const int wcol = w0 + pcol;
    float4 nz = *reinterpret_cast<const float4*>(noise + h * RES + wcol);
    float nzv[4] = {nz.x, nz.y, nz.z, nz.w};

    #pragma unroll
    for (int i = 0; i < 8; i++) {
        const int oc = oc0 + ocg * 8 + i;
        const float d  = g_dcoef[b * COUT + oc];
        const float bi = bias[oc];
        float4 r;
        float* rp = &r.x;
        #pragma unroll
        for (int j = 0; j < 4; j++) {
            float v = acc[i][j] * d + nzv[j] * ns + bi;
            v = (v > 0.f ? v : LRELU * v) * GAINV;
            rp[j] = v;
        }
        *reinterpret_cast<float4*>(
            out + (((size_t)b * COUT + oc) * RES + h) * RES + wcol) = r;
    }
}

// ---------------------------------------------------------------------------
extern "C" void kernel_launch(void* const* d_in, const int* in_sizes, int n_in,
                              void* d_out, int out_size) {
    const float* x    = (const float*)d_in[0];  // [B, CIN, RES, RES]
    const float* w    = (const float*)d_in[1];  // [B, WDIM]
    const float* wt   = (const float*)d_in[2];  // [COUT, CIN, 3, 3]
    const float* aw   = (const float*)d_in[3];  // [CIN, WDIM]
    const float* ab   = (const float*)d_in[4];  // [CIN]
    const float* bias = (const float*)d_in[5];  // [COUT]
    const float* nz   = (const float*)d_in[6];  // [RES, RES]
    const float* ns   = (const float*)d_in[7];  // [1]
    float* out = (float*)d_out;

    // styles: B*CIN warps
    styles_kernel<<<(B * CIN * 32 + 255) / 256, 256>>>(w, aw, ab);
    // wsq: COUT*CIN elements
    wsq_kernel<<<(COUT * CIN + 255) / 256, 256>>>(wt);
    // dcoef: B*COUT warps
    dcoef_kernel<<<(B * COUT * 32 + 255) / 256, 256>>>();
    // conv: (spatial tiles, oc tiles, batch)
    dim3 grid(16, COUT / OC_TILE, B);
    conv_kernel<<<grid, 256>>>(x, wt, bias, nz, ns, out);
}

// round 3
// speedup vs baseline: 4.3348x; 4.3348x over previous
#include <cuda_runtime.h>
#include <cuda.h>
#include <cuda_fp16.h>
#include <cstdint>

#define B     16
#define CIN   512
#define COUT  512
#define WDIM  512
#define RES   64
#define LRELU 0.2f
#define GAINV 1.4142135623730951f
#define PADW  66
#define NPIX  (PADW * PADW)   // 4356

// ---------------- scratch (device globals; no allocation allowed) ----------
__device__ float g_styles[B * CIN];
__device__ float g_wsq[COUT * CIN];
__device__ float g_dcoef[B * COUT];
__device__ __align__(1024) __half g_xs_hi[(size_t)B * NPIX * CIN];
__device__ __align__(1024) __half g_xs_lo[(size_t)B * NPIX * CIN];
__device__ __align__(1024) __half g_w_hi[(size_t)9 * COUT * CIN];
__device__ __align__(1024) __half g_w_lo[(size_t)9 * COUT * CIN];

// ---------------- PTX helpers ----------------------------------------------
__device__ __forceinline__ uint32_t smem_to_u32(const void* p) {
    uint32_t a;
    asm("{ .reg .u64 t; cvta.to.shared.u64 t, %1; cvt.u32.u64 %0, t; }"
        : "=r"(a) : "l"(p));
    return a;
}

#define MBARRIER_INIT(mbar, count) \
    asm volatile("mbarrier.init.shared.b64 [%0], %1;" \
        :: "r"((uint32_t)(mbar)), "r"((uint32_t)(count)) : "memory")
#define MBARRIER_EXPECT_TX(mbar, tx) \
    asm volatile("mbarrier.arrive.expect_tx.shared.b64 _, [%0], %1;" \
        :: "r"((uint32_t)(mbar)), "r"((uint32_t)(tx)) : "memory")
#define MBARRIER_ARRIVE(mbar) \
    asm volatile("mbarrier.arrive.shared.b64 _, [%0];" \
        :: "r"((uint32_t)(mbar)) : "memory")

#define MBARRIER_WAIT_PARITY(mbar, par) do { \
    uint32_t _m = (uint32_t)(mbar); uint32_t _p = (uint32_t)(par); uint32_t _d; \
    asm volatile("{\n\t.reg .pred p;\n\t" \
        "mbarrier.try_wait.parity.acquire.cta.shared::cta.b64 p, [%1], %2;\n\t" \
        "selp.b32 %0, 1, 0, p;\n\t}" : "=r"(_d) : "r"(_m), "r"(_p) : "memory"); \
    if (!_d) { \
        asm volatile("{\n\t.reg .pred P1;\n\tWL_%=:\n\t" \
            "mbarrier.try_wait.parity.acquire.cta.shared::cta.b64 P1, [%0], %1, 0x989680;\n\t" \
            "@P1 bra.uni WD_%=;\n\tbra.uni WL_%=;\n\tWD_%=:\n\t}" \
            :: "r"(_m), "r"(_p) : "memory"); \
    } } while (0)

#define MBARRIER_WAIT_PARITY_RELAXED(mbar, par) do { \
    uint32_t _m = (uint32_t)(mbar); uint32_t _p = (uint32_t)(par); uint32_t _d; \
    asm volatile("{\n\t.reg .pred p;\n\t" \
        "mbarrier.try_wait.parity.relaxed.cta.shared::cta.b64 p, [%1], %2, 0x989680;\n\t" \
        "selp.b32 %0, 1, 0, p;\n\t}" : "=r"(_d) : "r"(_m), "r"(_p) : "memory"); \
    if (!_d) { \
        asm volatile("{\n\t.reg .pred P1;\n\tWL_%=:\n\t" \
            "mbarrier.try_wait.parity.relaxed.cta.shared::cta.b64 P1, [%0], %1, 0x989680;\n\t" \
            "@P1 bra.uni WD_%=;\n\tbra.uni WL_%=;\n\tWD_%=:\n\t}" \
            :: "r"(_m), "r"(_p) : "memory"); \
    } } while (0)

#define TMA_LOAD_3D(smem_addr, tmap, cx, cy, cz, mbar) \
    asm volatile("cp.async.bulk.tensor.3d.shared::cta.global.tile.mbarrier::complete_tx::bytes " \
        "[%0], [%1, {%2, %3, %4}], [%5];" \
        :: "r"((uint32_t)(smem_addr)), "l"(tmap), "r"((int32_t)(cx)), \
           "r"((int32_t)(cy)), "r"((int32_t)(cz)), "r"((uint32_t)(mbar)) : "memory")

__device__ __forceinline__ void ldsm4(uint32_t* r, uint32_t addr) {
    asm volatile("ldmatrix.sync.aligned.m8n8.x4.shared.b16 {%0,%1,%2,%3}, [%4];"
        : "=r"(r[0]), "=r"(r[1]), "=r"(r[2]), "=r"(r[3]) : "r"(addr));
}
__device__ __forceinline__ void mma16816(float* c, const uint32_t* a,
                                         const uint32_t* b) {
    asm volatile("mma.sync.aligned.m16n8k16.row.col.f32.f16.f16.f32 "
        "{%0,%1,%2,%3}, {%4,%5,%6,%7}, {%8,%9}, {%0,%1,%2,%3};"
        : "+f"(c[0]), "+f"(c[1]), "+f"(c[2]), "+f"(c[3])
        : "r"(a[0]), "r"(a[1]), "r"(a[2]), "r"(a[3]), "r"(b[0]), "r"(b[1]));
}

// ---------------------------------------------------------------------------
// Prep kernels
// ---------------------------------------------------------------------------
__global__ void styles_kernel(const float* __restrict__ w,
                              const float* __restrict__ aw,
                              const float* __restrict__ ab) {
    int warp = (blockIdx.x * blockDim.x + threadIdx.x) >> 5;
    int lane = threadIdx.x & 31;
    if (warp >= B * CIN) return;
    int b = warp / CIN, c = warp % CIN;
    const float* wr = w + b * WDIM;
    const float* ar = aw + c * WDIM;
    float sum = 0.f;
    for (int d = lane; d < WDIM; d += 32) sum += wr[d] * ar[d];
    #pragma unroll
    for (int o = 16; o; o >>= 1) sum += __shfl_xor_sync(0xffffffffu, sum, o);
    if (lane == 0) g_styles[warp] = sum * 0.044194173824159216f + ab[c];
}

__global__ void wsq_kernel(const float* __restrict__ weight) {
    int i = blockIdx.x * blockDim.x + threadIdx.x;
    if (i >= COUT * CIN) return;
    const float* p = weight + (size_t)i * 9;
    float s = 0.f;
    #pragma unroll
    for (int k = 0; k < 9; k++) s += p[k] * p[k];
    g_wsq[i] = s;
}

__global__ void dcoef_kernel() {
    int warp = (blockIdx.x * blockDim.x + threadIdx.x) >> 5;
    int lane = threadIdx.x & 31;
    if (warp >= B * COUT) return;
    int b = warp / COUT, o = warp % COUT;
    const float* sr = g_styles + b * CIN;
    const float* wr = g_wsq + o * CIN;
    float sum = 0.f;
    for (int c = lane; c < CIN; c += 32) {
        float s = sr[c];
        sum += s * s * wr[c];
    }
    #pragma unroll
    for (int k = 16; k; k >>= 1) sum += __shfl_xor_sync(0xffffffffu, sum, k);
    if (lane == 0) g_dcoef[warp] = rsqrtf(sum + 1e-8f);
}

__global__ void wsplit_kernel(const float* __restrict__ wt) {
    int i = blockIdx.x * blockDim.x + threadIdx.x;
    if (i >= COUT * CIN * 9) return;
    int cin = i % CIN;
    int rest = i / CIN;
    int oc = rest % COUT;
    int tap = rest / COUT;
    float v = wt[((size_t)oc * CIN + cin) * 9 + tap];
    __half hv = __float2half_rn(v);
    __half lv = __float2half_rn(v - __half2float(hv));
    size_t o = ((size_t)tap * COUT + oc) * CIN + cin;
    g_w_hi[o] = hv;
    g_w_lo[o] = lv;
}

__global__ void xborder_kernel() {
    int r = blockIdx.x * blockDim.x + threadIdx.x;
    if (r >= B * NPIX) return;
    int pp = r % NPIX;
    int pr = pp / PADW, pc = pp % PADW;
    if (pr == 0 || pr == PADW - 1 || pc == 0 || pc == PADW - 1) {
        uint4 z = {0, 0, 0, 0};
        uint4* a = (uint4*)(g_xs_hi + (size_t)r * CIN);
        uint4* c = (uint4*)(g_xs_lo + (size_t)r * CIN);
        #pragma unroll 4
        for (int k = 0; k < CIN / 8; k++) { a[k] = z; c[k] = z; }
    }
}

__global__ __launch_bounds__(256) void xsplit_kernel(const float* __restrict__ x) {
    __shared__ float s[64][65];
    int h = blockIdx.x, b = blockIdx.y;
    int tid = threadIdx.x;
    int rowbase = (h + 1) * PADW + 1;
    for (int c0 = 0; c0 < CIN; c0 += 64) {
        #pragma unroll
        for (int i = tid; i < 4096; i += 256) {
            int cc = i >> 6, w = i & 63;
            s[cc][w] = x[(((size_t)b * CIN + c0 + cc) * RES + h) * RES + w]
                       * g_styles[b * CIN + c0 + cc];
        }
        __syncthreads();
        #pragma unroll
        for (int i = tid; i < 4096; i += 256) {
            int w = i >> 6, cc = i & 63;
            float v = s[cc][w];
            __half hv = __float2half_rn(v);
            __half lv = __float2half_rn(v - __half2float(hv));
            size_t o = ((size_t)b * NPIX + rowbase + w) * CIN + c0 + cc;
            g_xs_hi[o] = hv;
            g_xs_lo[o] = lv;
        }
        __syncthreads();
    }
}

// ---------------------------------------------------------------------------
// Main HMMA conv kernel.
// Grid (32 n-tiles, 4 m-tiles, 16 b). 288 threads = 8 compute warps + 1 TMA.
// CTA tile: M=128 oc x N=128 pixels (2 output rows). Warp tile m64 x n32.
// K loop: 3 passes x 8 cin-chunks(64) x 9 taps. B = union x-tile (264 rows).
// ---------------------------------------------------------------------------
#define A_STAGES 4
#define B_STAGES 2
#define A_BYTES  16384          // 128 oc rows x 128B
#define B_SEG    17408          // 136 rows slot (132 used), 1024-aligned
#define B_BYTES  (2 * B_SEG)    // 34816
#define B_TX     33792          // 264 * 128 actual bytes

// smem offsets (from 1024-aligned base)
#define OFF_AF(s)  ((s) * 8)          // A-full
#define OFF_AE(s)  (32 + (s) * 8)     // A-empty
#define OFF_BF(s)  (64 + (s) * 8)
#define OFF_BE(s)  (80 + (s) * 8)
#define OFF_A(s)   (1024 + (s) * A_BYTES)
#define OFF_B(s)   (1024 + A_STAGES * A_BYTES + (s) * B_BYTES)
#define SMEM_USED  (1024 + A_STAGES * A_BYTES + B_STAGES * B_BYTES)  // 136192
#define SMEM_TOTAL (SMEM_USED + 1024)                                // align slack

__global__ void __launch_bounds__(288, 1) conv_mma_kernel(
    const __grid_constant__ CUtensorMap tm_whi,
    const __grid_constant__ CUtensorMap tm_wlo,
    const __grid_constant__ CUtensorMap tm_xhi,
    const __grid_constant__ CUtensorMap tm_xlo,
    const float* __restrict__ bias, const float* __restrict__ noise,
    const float* __restrict__ nstrength, float* __restrict__ out)
{
    extern __shared__ char smem_raw[];
    uint32_t sb = (smem_to_u32(smem_raw) + 1023u) & ~1023u;

    const int tid  = threadIdx.x;
    const int wid  = tid >> 5;
    const int lane = tid & 31;
    const int p0 = blockIdx.x * 128;        // output pixel base (2 rows of 64)
    const int h0 = blockIdx.x * 2;
    const int m0 = blockIdx.y * 128;        // oc base
    const int b  = blockIdx.z;

    if (tid == 0) {
        #pragma unroll
        for (int s = 0; s < A_STAGES; s++) {
            MBARRIER_INIT(sb + OFF_AF(s), 1);
            MBARRIER_INIT(sb + OFF_AE(s), 8);   // 8 warp-leaders arrive
        }
        #pragma unroll
        for (int s = 0; s < B_STAGES; s++) {
            MBARRIER_INIT(sb + OFF_BF(s), 1);
            MBARRIER_INIT(sb + OFF_BE(s), 8);
        }
    }
    __syncthreads();

    if (wid == 8) {
        // -------- producer --------
        if (lane == 0) {
            int sa = 0, pa = 1, sbt = 0, pb = 1;
            const int pixstart = h0 * PADW;
            for (int pass = 0; pass < 3; pass++) {
                const CUtensorMap* mw = (pass == 2) ? &tm_wlo : &tm_whi;
                const CUtensorMap* mx = (pass == 1) ? &tm_xlo : &tm_xhi;
                for (int kc = 0; kc < 8; kc++) {
                    MBARRIER_WAIT_PARITY_RELAXED(sb + OFF_BE(sbt), pb);
                    uint32_t bf = sb + OFF_BF(sbt);
                    MBARRIER_EXPECT_TX(bf, B_TX);
                    uint32_t bst = sb + OFF_B(sbt);
                    TMA_LOAD_3D(bst,         mx, kc * 64, pixstart,       b, bf);
                    TMA_LOAD_3D(bst + B_SEG, mx, kc * 64, pixstart + 132, b, bf);
                    if (++sbt == B_STAGES) { sbt = 0; pb ^= 1; }
                    for (int tap = 0; tap < 9; tap++) {
                        MBARRIER_WAIT_PARITY_RELAXED(sb + OFF_AE(sa), pa);
                        uint32_t af = sb + OFF_AF(sa);
                        MBARRIER_EXPECT_TX(af, A_BYTES);
                        TMA_LOAD_3D(sb + OFF_A(sa), mw, kc * 64, m0, tap, af);
                        if (++sa == A_STAGES) { sa = 0; pa ^= 1; }
                    }
                }
            }
        }
        return;
    }

    // -------- compute warps 0..7 --------
    const int wm = wid & 1;          // 2 m sub-tiles of 64
    const int wn = wid >> 1;         // 4 n sub-tiles of 32

    // A addressing (fixed rows)
    const int ach = lane >> 4;                 // k-half select
    uint32_t arb[4]; int ap[4];
    #pragma unroll
    for (int mi = 0; mi < 4; mi++) {
        int row = wm * 64 + mi * 16 + (lane & 15);
        arb[mi] = row * 128;
        ap[mi]  = row & 7;
    }
    // B addressing (fixed n -> hl,w; rows vary by tap)
    const int bch = (lane >> 3) & 1;
    int hl[2], wc[2];
    #pragma unroll
    for (int nb2 = 0; nb2 < 2; nb2++) {
        int nl = wn * 32 + nb2 * 16 + (lane & 7) + ((lane >> 4) & 1) * 8;
        hl[nb2] = nl >> 6;
        wc[nb2] = nl & 63;
    }

    float acc[4][4][4];
    #pragma unroll
    for (int mi = 0; mi < 4; mi++)
        #pragma unroll
        for (int ni = 0; ni < 4; ni++)
            #pragma unroll
            for (int k = 0; k < 4; k++) acc[mi][ni][k] = 0.f;

    int sa = 0, pa = 0, sbt = 0, pb = 0;
    for (int it24 = 0; it24 < 24; it24++) {   // pass*8 + kc
        MBARRIER_WAIT_PARITY(sb + OFF_BF(sbt), pb);
        const uint32_t bst = sb + OFF_B(sbt);
        #pragma unroll
        for (int tap = 0; tap < 9; tap++) {
            const int dy = tap / 3, dx = tap % 3;
            MBARRIER_WAIT_PARITY(sb + OFF_AF(sa), pa);
            const uint32_t ast = sb + OFF_A(sa);

            uint32_t brb[2]; int bp[2];
            #pragma unroll
            for (int nb2 = 0; nb2 < 2; nb2++) {
                int rsum = hl[nb2] + dy;
                int seg  = rsum >> 1;
                int rloc = (rsum & 1) * PADW + wc[nb2] + dx;
                brb[nb2] = seg * B_SEG + rloc * 128;
                bp[nb2]  = rloc & 7;
            }
            #pragma unroll
            for (int ks = 0; ks < 4; ks++) {
                uint32_t a[4][4], bf[2][4];
                #pragma unroll
                for (int mi = 0; mi < 4; mi++)
                    ldsm4(a[mi], ast + arb[mi] +
                          ((uint32_t)((ks * 2 + ach) ^ ap[mi]) << 4));
                #pragma unroll
                for (int nb2 = 0; nb2 < 2; nb2++)
                    ldsm4(bf[nb2], bst + brb[nb2] +
                          ((uint32_t)((ks * 2 + bch) ^ bp[nb2]) << 4));
                #pragma unroll
                for (int mi = 0; mi < 4; mi++)
                    #pragma unroll
                    for (int ng = 0; ng < 4; ng++)
                        mma16816(acc[mi][ng], a[mi], &bf[ng >> 1][(ng & 1) * 2]);
            }
            __syncwarp();
            if (lane == 0) MBARRIER_ARRIVE(sb + OFF_AE(sa));
            if (++sa == A_STAGES) { sa = 0; pa ^= 1; }
        }
        __syncwarp();
        if (lane == 0) MBARRIER_ARRIVE(sb + OFF_BE(sbt));
        if (++sbt == B_STAGES) { sbt = 0; pb ^= 1; }
    }

    // -------- epilogue --------
    const float ns = nstrength[0];
    #pragma unroll
    for (int mi = 0; mi < 4; mi++) {
        const int mrow = m0 + wm * 64 + mi * 16 + (lane >> 2);
        const float dc0 = g_dcoef[b * COUT + mrow];
        const float dc1 = g_dcoef[b * COUT + mrow + 8];
        const float bv0 = bias[mrow];
        const float bv1 = bias[mrow + 8];
        #pragma unroll
        for (int ni = 0; ni < 4; ni++) {
            const int pix = p0 + wn * 32 + ni * 8 + ((lane & 3) << 1);
            const float2 nzv = *reinterpret_cast<const float2*>(noise + pix);
            float v0 = acc[mi][ni][0] * dc0 + nzv.x * ns + bv0;
            float v1 = acc[mi][ni][1] * dc0 + nzv.y * ns + bv0;
            float v2 = acc[mi][ni][2] * dc1 + nzv.x * ns + bv1;
            float v3 = acc[mi][ni][3] * dc1 + nzv.y * ns + bv1;
            v0 = (v0 > 0.f ? v0 : LRELU * v0) * GAINV;
            v1 = (v1 > 0.f ? v1 : LRELU * v1) * GAINV;
            v2 = (v2 > 0.f ? v2 : LRELU * v2) * GAINV;
            v3 = (v3 > 0.f ? v3 : LRELU * v3) * GAINV;
            float2 r0 = {v0, v1}, r1 = {v2, v3};
            *reinterpret_cast<float2*>(
                out + ((size_t)(b * COUT + mrow) * 4096) + pix) = r0;
            *reinterpret_cast<float2*>(
                out + ((size_t)(b * COUT + mrow + 8) * 4096) + pix) = r1;
        }
    }
}

// ---------------------------------------------------------------------------
// Host launch
// ---------------------------------------------------------------------------
typedef CUresult (*PFN_tmapEncode)(
    CUtensorMap*, CUtensorMapDataType, cuuint32_t, void*,
    const cuuint64_t*, const cuuint64_t*, const cuuint32_t*, const cuuint32_t*,
    CUtensorMapInterleave, CUtensorMapSwizzle, CUtensorMapL2promotion,
    CUtensorMapFloatOOBfill);

static void make_map_3d(PFN_tmapEncode enc, CUtensorMap* m, void* base,
                        cuuint64_t d0, cuuint64_t d1, cuuint64_t d2,
                        cuuint64_t s1, cuuint64_t s2,
                        cuuint32_t b0, cuuint32_t b1) {
    cuuint64_t dims[3] = {d0, d1, d2};
    cuuint64_t strides[2] = {s1, s2};
    cuuint32_t box[3] = {b0, b1, 1};
    cuuint32_t es[3] = {1, 1, 1};
    enc(m, CU_TENSOR_MAP_DATA_TYPE_FLOAT16, 3, base, dims, strides, box, es,
        CU_TENSOR_MAP_INTERLEAVE_NONE, CU_TENSOR_MAP_SWIZZLE_128B,
        CU_TENSOR_MAP_L2_PROMOTION_L2_128B, CU_TENSOR_MAP_FLOAT_OOB_FILL_NONE);
}

extern "C" void kernel_launch(void* const* d_in, const int* in_sizes, int n_in,
                              void* d_out, int out_size) {
    const float* x    = (const float*)d_in[0];
    const float* w    = (const float*)d_in[1];
    const float* wt   = (const float*)d_in[2];
    const float* aw   = (const float*)d_in[3];
    const float* ab   = (const float*)d_in[4];
    const float* bias = (const float*)d_in[5];
    const float* nz   = (const float*)d_in[6];
    const float* ns   = (const float*)d_in[7];
    float* out = (float*)d_out;

    styles_kernel<<<(B * CIN * 32 + 255) / 256, 256>>>(w, aw, ab);
    wsq_kernel<<<(COUT * CIN + 255) / 256, 256>>>(wt);
    dcoef_kernel<<<(B * COUT * 32 + 255) / 256, 256>>>();
    wsplit_kernel<<<(COUT * CIN * 9 + 255) / 256, 256>>>(wt);
    xborder_kernel<<<(B * NPIX + 255) / 256, 256>>>();
    xsplit_kernel<<<dim3(RES, B), 256>>>(x);

    void* encp = nullptr;
    cudaDriverEntryPointQueryResult qr;
    cudaGetDriverEntryPointByVersion("cuTensorMapEncodeTiled", &encp, 12000,
                                     cudaEnableDefault, &qr);
    PFN_tmapEncode enc = (PFN_tmapEncode)encp;

    void *p_whi, *p_wlo, *p_xhi, *p_xlo;
    cudaGetSymbolAddress(&p_whi, g_w_hi);
    cudaGetSymbolAddress(&p_wlo, g_w_lo);
    cudaGetSymbolAddress(&p_xhi, g_xs_hi);
    cudaGetSymbolAddress(&p_xlo, g_xs_lo);

    CUtensorMap tm_whi, tm_wlo, tm_xhi, tm_xlo;
    // weights: (cin=512, oc=512, tap=9), box (64,128)
    make_map_3d(enc, &tm_whi, p_whi, CIN, COUT, 9,
                (cuuint64_t)CIN * 2, (cuuint64_t)COUT * CIN * 2, 64, 128);
    make_map_3d(enc, &tm_wlo, p_wlo, CIN, COUT, 9,
                (cuuint64_t)CIN * 2, (cuuint64_t)COUT * CIN * 2, 64, 128);
    // xs: (cin=512, pix=4356, b=16), box (64,132)
    make_map_3d(enc, &tm_xhi, p_xhi, CIN, NPIX, B,
                (cuuint64_t)CIN * 2, (cuuint64_t)NPIX * CIN * 2, 64, 132);
    make_map_3d(enc, &tm_xlo, p_xlo, CIN, NPIX, B,
                (cuuint64_t)CIN * 2, (cuuint64_t)NPIX * CIN * 2, 64, 132);

    cudaFuncSetAttribute(conv_mma_kernel,
                         cudaFuncAttributeMaxDynamicSharedMemorySize, SMEM_TOTAL);
    dim3 grid(32, 4, B);
    conv_mma_kernel<<<grid, 288, SMEM_TOTAL>>>(tm_whi, tm_wlo, tm_xhi, tm_xlo,
                                               bias, nz, ns, out);
}